// round 1
// baseline (speedup 1.0000x reference)
#include <cuda_runtime.h>
#include <math.h>

#define Bsz  128
#define Cch  256
#define Tt   30
#define Hh   16
#define Ww   11
#define NB   31
#define RED  16
#define OUTC 256
#define KCLS 10000
#define CR   4096   // Cch*RED

// -------- scratch (device globals; no runtime allocation allowed) --------
__device__ float g_p[(size_t)NB*Bsz*Tt*Cch];       // [n][B][T][C]   ~122 MB
__device__ float g_pmax[NB*Bsz*Cch];               // [n][B][C]
__device__ float g_pooled[(size_t)NB*Bsz*CR];      // [n][B][C*r]    ~65 MB
__device__ float g_feat[NB*Bsz*Cch];               // [n][B][C]
__device__ float g_outputs[NB*Bsz*OUTC];           // [n][B][O]
__device__ float g_bnn[NB*Bsz*OUTC];               // [n][B][O]
__device__ float g_scale[NB*OUTC];
__device__ float g_shift[NB*OUTC];
__device__ float g_colinv[NB*KCLS];

// -------- packed fp32x2 helpers (Blackwell full-rate fp32 path) --------
__device__ __forceinline__ unsigned long long pack2(float lo, float hi) {
  unsigned long long r;
  asm("mov.b64 %0, {%1, %2};" : "=l"(r) : "f"(lo), "f"(hi));
  return r;
}
__device__ __forceinline__ unsigned long long fma2(unsigned long long a,
                                                   unsigned long long b,
                                                   unsigned long long c) {
  unsigned long long d;
  asm("fma.rn.f32x2 %0, %1, %2, %3;" : "=l"(d) : "l"(a), "l"(b), "l"(c));
  return d;
}
__device__ __forceinline__ float2 unpack2(unsigned long long v) {
  float lo, hi;
  asm("mov.b64 {%0, %1}, %2;" : "=f"(lo), "=f"(hi) : "l"(v));
  return make_float2(lo, hi);
}

// ========== K1: horizontal strip pooling (mean+max per strip) ==========
// grid (B*T, C/32), 1024 threads: warp w handles channel c0+w for one (b,t).
__global__ void __launch_bounds__(1024) k_strip(const float* __restrict__ x) {
  int bt = blockIdx.x;
  int b = bt / Tt, t = bt % Tt;
  int warp = threadIdx.x >> 5;
  int lane = threadIdx.x & 31;
  int c = blockIdx.y * 32 + warp;

  __shared__ float sm[NB][33];

  const float* base = x + (((size_t)(b*Cch + c)*Tt + t) * Hh) * Ww;
  float s = 0.f, m = -INFINITY;
  if (lane < 16) {
    const float* row = base + lane * Ww;
#pragma unroll
    for (int w = 0; w < Ww; w++) { float v = row[w]; s += v; m = fmaxf(m, v); }
  }
  // hierarchical strip combine via shuffles (lanes >=16 hold neutral values)
  if (lane < 16) sm[15 + lane][warp] = s * (1.f/11.f) + m;               // p=16
  float s2 = s + __shfl_down_sync(0xffffffffu, s, 1);
  float m2 = fmaxf(m, __shfl_down_sync(0xffffffffu, m, 1));
  if (lane < 16 && (lane & 1) == 0) sm[7 + (lane>>1)][warp] = s2*(1.f/22.f) + m2;   // p=8
  float s4 = s2 + __shfl_down_sync(0xffffffffu, s2, 2);
  float m4 = fmaxf(m2, __shfl_down_sync(0xffffffffu, m2, 2));
  if (lane < 16 && (lane & 3) == 0) sm[3 + (lane>>2)][warp] = s4*(1.f/44.f) + m4;   // p=4
  float s8 = s4 + __shfl_down_sync(0xffffffffu, s4, 4);
  float m8 = fmaxf(m4, __shfl_down_sync(0xffffffffu, m4, 4));
  if (lane < 16 && (lane & 7) == 0) sm[1 + (lane>>3)][warp] = s8*(1.f/88.f) + m8;   // p=2
  float s16 = s8 + __shfl_down_sync(0xffffffffu, s8, 8);
  float m16 = fmaxf(m8, __shfl_down_sync(0xffffffffu, m8, 8));
  if (lane == 0) sm[0][warp] = s16*(1.f/176.f) + m16;                               // p=1
  __syncthreads();

  int tid = threadIdx.x;
  if (tid < NB * 32) {
    int bin = tid >> 5, col = tid & 31;
    int cc = blockIdx.y * 32 + col;
    g_p[(((size_t)bin*Bsz + b)*Tt + t)*Cch + cc] = sm[bin][col];
  }
}

// ========== K2: per (n,b) GMPA front (mask softmax, pooled, pmax) ==========
__global__ void __launch_bounds__(256) k_gmpa(const float* __restrict__ Wmask) {
  int b = blockIdx.x, n = blockIdx.y;
  __shared__ float sp[Tt*Cch];    // 7680 floats
  __shared__ float swm[Cch*RED];  // 4096 floats
  __shared__ float sm[Tt*RED];    // logits -> mask (in place)
  int tid = threadIdx.x;

  const float* pg = g_p + ((size_t)(n*Bsz + b)) * (Tt*Cch);
  for (int i = tid; i < Tt*Cch; i += 256) sp[i] = pg[i];
  for (int i = tid; i < Cch*RED; i += 256) swm[i] = Wmask[(size_t)n*Cch*RED + i];
  __syncthreads();

  // A[t][r] = sum_c p[t][c] * Wmask[c][r]
  for (int idx = tid; idx < Tt*RED; idx += 256) {
    int t = idx / RED, r = idx % RED;
    const float* pr = sp + t*Cch;
    float acc = 0.f;
#pragma unroll 8
    for (int c = 0; c < Cch; c++) acc += pr[c] * swm[c*RED + r];
    sm[idx] = acc;
  }
  __syncthreads();

  // softmax over t, per r
  if (tid < RED) {
    float mx = -INFINITY;
    for (int t = 0; t < Tt; t++) mx = fmaxf(mx, sm[t*RED + tid]);
    float s = 0.f;
    for (int t = 0; t < Tt; t++) { float e = expf(sm[t*RED + tid] - mx); sm[t*RED + tid] = e; s += e; }
    float inv = 1.f / s;
    for (int t = 0; t < Tt; t++) sm[t*RED + tid] *= inv;
  }
  __syncthreads();

  // pooled[c*16+r] = sum_t p[t][c]*mask[t][r]
  float* pooled = g_pooled + ((size_t)(n*Bsz + b)) * CR;
  for (int idx = tid; idx < CR; idx += 256) {
    int c = idx >> 4, r = idx & 15;
    float acc = 0.f;
#pragma unroll
    for (int t = 0; t < Tt; t++) acc += sp[t*Cch + c] * sm[t*RED + r];
    pooled[idx] = acc;
  }

  // pmax[c] = max_t p[t][c]
  {
    int c = tid;
    float mx = -INFINITY;
#pragma unroll
    for (int t = 0; t < Tt; t++) mx = fmaxf(mx, sp[t*Cch + c]);
    g_pmax[(size_t)(n*Bsz + b)*Cch + c] = mx;
  }
}

// ========== K3: 128xK @ Kx256 GEMM, 64-col tiles, f32x2 inner ==========
// mode 0: out = pooled@Wout -> leaky -> feat = pmax + out
// mode 1: outputs = feat@FForward -> g_outputs + d_out (transposed)
__global__ void __launch_bounds__(256) k_gemm64(const float* __restrict__ Bmat,
                                                int K, int mode,
                                                float* __restrict__ dout) {
  int n = blockIdx.y;
  int col0 = blockIdx.x * 64;
  __shared__ __align__(16) float sA[32*132];
  __shared__ __align__(16) float sB[32*64];
  int tid = threadIdx.x;
  int tx = tid & 15, ty = tid >> 4;

  const float* Ag = (mode == 0) ? (g_pooled + (size_t)n*Bsz*CR)
                                : (g_feat   + (size_t)n*Bsz*OUTC);
  const float* Bg = Bmat + (size_t)n*K*Cch;

  unsigned long long acc[4][4];
#pragma unroll
  for (int i = 0; i < 4; i++)
#pragma unroll
    for (int j = 0; j < 4; j++) acc[i][j] = 0ull;

  int rA = tid >> 5, kA = tid & 31;
  int cB = tid & 63, kB = tid >> 6;

  for (int k0 = 0; k0 < K; k0 += 32) {
#pragma unroll
    for (int i = 0; i < 16; i++)
      sA[kA*132 + rA + i*8] = Ag[(size_t)(rA + i*8)*K + (k0 + kA)];
#pragma unroll
    for (int i = 0; i < 8; i++)
      sB[(kB + i*4)*64 + cB] = Bg[(size_t)(k0 + kB + i*4)*Cch + col0 + cB];
    __syncthreads();

#pragma unroll
    for (int kk = 0; kk < 32; kk++) {
      const float* ap = sA + kk*132 + ty*8;
      ulonglong2 a01 = *(const ulonglong2*)ap;
      ulonglong2 a23 = *(const ulonglong2*)(ap + 4);
      const float* bp = sB + kk*64 + tx;
#pragma unroll
      for (int j = 0; j < 4; j++) {
        float bv = bp[j*16];
        unsigned long long bb = pack2(bv, bv);
        acc[0][j] = fma2(a01.x, bb, acc[0][j]);
        acc[1][j] = fma2(a01.y, bb, acc[1][j]);
        acc[2][j] = fma2(a23.x, bb, acc[2][j]);
        acc[3][j] = fma2(a23.y, bb, acc[3][j]);
      }
    }
    __syncthreads();
  }

#pragma unroll
  for (int pi = 0; pi < 4; pi++) {
    int row = ty*8 + pi*2;
#pragma unroll
    for (int j = 0; j < 4; j++) {
      int c = col0 + tx + j*16;
      float2 v = unpack2(acc[pi][j]);
      if (mode == 0) {
        float l0 = v.x >= 0.f ? v.x : 0.01f * v.x;
        float l1 = v.y >= 0.f ? v.y : 0.01f * v.y;
        g_feat[(size_t)(n*Bsz + row)*Cch + c]       = g_pmax[(size_t)(n*Bsz + row)*Cch + c] + l0;
        g_feat[(size_t)(n*Bsz + row + 1)*Cch + c]   = g_pmax[(size_t)(n*Bsz + row + 1)*Cch + c] + l1;
      } else {
        g_outputs[(size_t)(n*Bsz + row)*OUTC + c]     = v.x;
        g_outputs[(size_t)(n*Bsz + row + 1)*OUTC + c] = v.y;
        dout[((size_t)row*NB + n)*OUTC + c]       = v.x;
        dout[((size_t)(row+1)*NB + n)*OUTC + c]   = v.y;
      }
    }
  }
}

// ========== K4: BatchNorm stats over B per (n,o) ==========
__global__ void k_bnstats(const float* __restrict__ gamma,
                          const float* __restrict__ beta) {
  int n = blockIdx.x;
  int o = threadIdx.x;
  const float* base = g_outputs + (size_t)n*Bsz*OUTC + o;
  float s = 0.f;
  for (int b = 0; b < Bsz; b++) s += base[(size_t)b*OUTC];
  float mean = s * (1.f/Bsz);
  float v = 0.f;
  for (int b = 0; b < Bsz; b++) { float d = base[(size_t)b*OUTC] - mean; v += d*d; }
  v *= (1.f/Bsz);
  float sc = gamma[n*OUTC + o] / sqrtf(v + 1e-5f);
  g_scale[n*OUTC + o] = sc;
  g_shift[n*OUTC + o] = beta[n*OUTC + o] - mean * sc;
}

// ========== K5: apply BN + L2-normalize per (n,b) ==========
__global__ void __launch_bounds__(256) k_bnn() {
  int b = blockIdx.x, n = blockIdx.y;
  int o = threadIdx.x;
  float v = g_scale[n*OUTC + o] * g_outputs[(size_t)(n*Bsz + b)*OUTC + o] + g_shift[n*OUTC + o];
  float ss = v * v;
#pragma unroll
  for (int off = 16; off; off >>= 1) ss += __shfl_down_sync(0xffffffffu, ss, off);
  __shared__ float red[8];
  __shared__ float invn;
  if ((o & 31) == 0) red[o >> 5] = ss;
  __syncthreads();
  if (o == 0) {
    float s = 0.f;
#pragma unroll
    for (int i = 0; i < 8; i++) s += red[i];
    invn = 1.f / fmaxf(sqrtf(s), 1e-12f);
  }
  __syncthreads();
  g_bnn[(size_t)(n*Bsz + b)*OUTC + o] = v * invn;
}

// ========== K6: classifier column inverse norms ==========
__global__ void k_colnorm(const float* __restrict__ fc) {
  int n = blockIdx.y;
  int k = blockIdx.x * 256 + threadIdx.x;
  if (k >= KCLS) return;
  const float* base = fc + (size_t)n*OUTC*KCLS + k;
  float ss = 0.f;
#pragma unroll 4
  for (int o = 0; o < OUTC; o++) { float v = base[(size_t)o*KCLS]; ss += v*v; }
  g_colinv[(size_t)n*KCLS + k] = 1.f / fmaxf(sqrtf(ss), 1e-12f);
}

// ========== K7: logits GEMM 128x10000 @ K=256, 128-col tiles ==========
__global__ void __launch_bounds__(256) k_logits(const float* __restrict__ fc,
                                                float* __restrict__ out) {
  int n = blockIdx.y;
  int col0 = blockIdx.x * 128;
  __shared__ __align__(16) float sA[32*132];
  __shared__ __align__(16) float sB[32*128];
  int tid = threadIdx.x;
  int tx = tid & 15, ty = tid >> 4;

  const float* Ag = g_bnn + (size_t)n*Bsz*OUTC;
  const float* Bg = fc + (size_t)n*OUTC*KCLS;

  unsigned long long acc[4][8];
#pragma unroll
  for (int i = 0; i < 4; i++)
#pragma unroll
    for (int j = 0; j < 8; j++) acc[i][j] = 0ull;

  int rA = tid >> 5, kA = tid & 31;
  int cB = tid & 127, kB = tid >> 7;

  for (int k0 = 0; k0 < OUTC; k0 += 32) {
#pragma unroll
    for (int i = 0; i < 16; i++)
      sA[kA*132 + rA + i*8] = Ag[(size_t)(rA + i*8)*OUTC + (k0 + kA)];
#pragma unroll
    for (int i = 0; i < 16; i++) {
      int kk = kB + i*2;
      int c = col0 + cB;
      sB[kk*128 + cB] = (c < KCLS) ? Bg[(size_t)(k0 + kk)*KCLS + c] : 0.f;
    }
    __syncthreads();

#pragma unroll
    for (int kk = 0; kk < 32; kk++) {
      const float* ap = sA + kk*132 + ty*8;
      ulonglong2 a01 = *(const ulonglong2*)ap;
      ulonglong2 a23 = *(const ulonglong2*)(ap + 4);
      const float* bp = sB + kk*128 + tx;
#pragma unroll
      for (int j = 0; j < 8; j++) {
        float bv = bp[j*16];
        unsigned long long bb = pack2(bv, bv);
        acc[0][j] = fma2(a01.x, bb, acc[0][j]);
        acc[1][j] = fma2(a01.y, bb, acc[1][j]);
        acc[2][j] = fma2(a23.x, bb, acc[2][j]);
        acc[3][j] = fma2(a23.y, bb, acc[3][j]);
      }
    }
    __syncthreads();
  }

#pragma unroll
  for (int pi = 0; pi < 4; pi++) {
    int row = ty*8 + pi*2;
#pragma unroll
    for (int j = 0; j < 8; j++) {
      int c = col0 + tx + j*16;
      if (c < KCLS) {
        float inv = g_colinv[(size_t)n*KCLS + c];
        float2 v = unpack2(acc[pi][j]);
        out[((size_t)row*NB + n)*KCLS + c]       = v.x * inv;
        out[((size_t)(row+1)*NB + n)*KCLS + c]   = v.y * inv;
      }
    }
  }
}

// ========== launch ==========
extern "C" void kernel_launch(void* const* d_in, const int* in_sizes, int n_in,
                              void* d_out, int out_size) {
  const float* x        = (const float*)d_in[0];
  const float* Wmask    = (const float*)d_in[1];
  const float* Wout     = (const float*)d_in[2];
  const float* FForward = (const float*)d_in[3];
  const float* gamma    = (const float*)d_in[4];
  const float* beta     = (const float*)d_in[5];
  const float* fc1d     = (const float*)d_in[6];
  float* out        = (float*)d_out;
  float* out_logits = out + (size_t)Bsz*NB*OUTC;

  k_strip  <<<dim3(Bsz*Tt, Cch/32), 1024>>>(x);
  k_gmpa   <<<dim3(Bsz, NB), 256>>>(Wmask);
  k_gemm64 <<<dim3(4, NB), 256>>>(Wout, CR, 0, nullptr);
  k_gemm64 <<<dim3(4, NB), 256>>>(FForward, OUTC, 1, out);
  k_bnstats<<<NB, OUTC>>>(gamma, beta);
  k_bnn    <<<dim3(Bsz, NB), 256>>>();
  k_colnorm<<<dim3((KCLS + 255)/256, NB), 256>>>(fc1d);
  k_logits <<<dim3((KCLS + 127)/128, NB), 256>>>(fc1d, out_logits);
}

// round 3
// speedup vs baseline: 1.1954x; 1.1954x over previous
#include <cuda_runtime.h>
#include <cuda_bf16.h>
#include <math.h>
#include <stdint.h>

#define Bsz  128
#define Cch  256
#define Tt   30
#define Hh   16
#define Ww   11
#define NB   31
#define RED  16
#define OUTC 256
#define KCLS 10000
#define CR   4096   // Cch*RED

// -------- scratch (device globals; no runtime allocation allowed) --------
__device__ float g_p[(size_t)NB*Bsz*Tt*Cch];       // [n][B][T][C]
__device__ float g_pmax[NB*Bsz*Cch];
__device__ __nv_bfloat16 g_pooled_hi[(size_t)NB*Bsz*CR];
__device__ __nv_bfloat16 g_pooled_lo[(size_t)NB*Bsz*CR];
__device__ float g_feat[NB*Bsz*Cch];
__device__ float g_outputs[NB*Bsz*OUTC];
__device__ float g_scale[NB*OUTC];
__device__ float g_shift[NB*OUTC];
__device__ __nv_bfloat16 g_bnn_hi[NB*Bsz*OUTC];
__device__ __nv_bfloat16 g_bnn_lo[NB*Bsz*OUTC];

// -------- packed fp32x2 helpers --------
__device__ __forceinline__ unsigned long long pack2(float lo, float hi) {
  unsigned long long r;
  asm("mov.b64 %0, {%1, %2};" : "=l"(r) : "f"(lo), "f"(hi));
  return r;
}
__device__ __forceinline__ unsigned long long fma2(unsigned long long a,
                                                   unsigned long long b,
                                                   unsigned long long c) {
  unsigned long long d;
  asm("fma.rn.f32x2 %0, %1, %2, %3;" : "=l"(d) : "l"(a), "l"(b), "l"(c));
  return d;
}
__device__ __forceinline__ float2 unpack2(unsigned long long v) {
  float lo, hi;
  asm("mov.b64 {%0, %1}, %2;" : "=f"(lo), "=f"(hi) : "l"(v));
  return make_float2(lo, hi);
}

// -------- warp-level bf16 MMA (m16n8k16), fp32 accumulate --------
__device__ __forceinline__ void mma_bf16(float* d, const uint32_t* a, const uint32_t* b) {
  asm volatile("mma.sync.aligned.m16n8k16.row.col.f32.bf16.bf16.f32 "
               "{%0,%1,%2,%3}, {%4,%5,%6,%7}, {%8,%9}, {%0,%1,%2,%3};"
               : "+f"(d[0]), "+f"(d[1]), "+f"(d[2]), "+f"(d[3])
               : "r"(a[0]), "r"(a[1]), "r"(a[2]), "r"(a[3]),
                 "r"(b[0]), "r"(b[1]));
}

// ========== K1: horizontal strip pooling (mean+max per strip) ==========
__global__ void __launch_bounds__(1024) k_strip(const float* __restrict__ x) {
  int bt = blockIdx.x;
  int b = bt / Tt, t = bt % Tt;
  int warp = threadIdx.x >> 5;
  int lane = threadIdx.x & 31;
  int c = blockIdx.y * 32 + warp;

  __shared__ float sm[NB][33];

  const float* base = x + (((size_t)(b*Cch + c)*Tt + t) * Hh) * Ww;
  float s = 0.f, m = -INFINITY;
  if (lane < 16) {
    const float* row = base + lane * Ww;
#pragma unroll
    for (int w = 0; w < Ww; w++) { float v = row[w]; s += v; m = fmaxf(m, v); }
  }
  if (lane < 16) sm[15 + lane][warp] = s * (1.f/11.f) + m;
  float s2 = s + __shfl_down_sync(0xffffffffu, s, 1);
  float m2 = fmaxf(m, __shfl_down_sync(0xffffffffu, m, 1));
  if (lane < 16 && (lane & 1) == 0) sm[7 + (lane>>1)][warp] = s2*(1.f/22.f) + m2;
  float s4 = s2 + __shfl_down_sync(0xffffffffu, s2, 2);
  float m4 = fmaxf(m2, __shfl_down_sync(0xffffffffu, m2, 2));
  if (lane < 16 && (lane & 3) == 0) sm[3 + (lane>>2)][warp] = s4*(1.f/44.f) + m4;
  float s8 = s4 + __shfl_down_sync(0xffffffffu, s4, 4);
  float m8 = fmaxf(m4, __shfl_down_sync(0xffffffffu, m4, 4));
  if (lane < 16 && (lane & 7) == 0) sm[1 + (lane>>3)][warp] = s8*(1.f/88.f) + m8;
  float s16 = s8 + __shfl_down_sync(0xffffffffu, s8, 8);
  float m16 = fmaxf(m8, __shfl_down_sync(0xffffffffu, m8, 8));
  if (lane == 0) sm[0][warp] = s16*(1.f/176.f) + m16;
  __syncthreads();

  int tid = threadIdx.x;
  if (tid < NB * 32) {
    int bin = tid >> 5, col = tid & 31;
    int cc = blockIdx.y * 32 + col;
    g_p[(((size_t)bin*Bsz + b)*Tt + t)*Cch + cc] = sm[bin][col];
  }
}

// ========== K2: per (n,b) GMPA front (emits pooled as bf16 hi/lo) ==========
__global__ void __launch_bounds__(256) k_gmpa(const float* __restrict__ Wmask) {
  int b = blockIdx.x, n = blockIdx.y;
  __shared__ float sp[Tt*Cch];
  __shared__ float swm[Cch*RED];
  __shared__ float sm[Tt*RED];
  int tid = threadIdx.x;

  const float* pg = g_p + ((size_t)(n*Bsz + b)) * (Tt*Cch);
  for (int i = tid; i < Tt*Cch; i += 256) sp[i] = pg[i];
  for (int i = tid; i < Cch*RED; i += 256) swm[i] = Wmask[(size_t)n*Cch*RED + i];
  __syncthreads();

  for (int idx = tid; idx < Tt*RED; idx += 256) {
    int t = idx / RED, r = idx % RED;
    const float* pr = sp + t*Cch;
    float acc = 0.f;
#pragma unroll 8
    for (int c = 0; c < Cch; c++) acc += pr[c] * swm[c*RED + r];
    sm[idx] = acc;
  }
  __syncthreads();

  if (tid < RED) {
    float mx = -INFINITY;
    for (int t = 0; t < Tt; t++) mx = fmaxf(mx, sm[t*RED + tid]);
    float s = 0.f;
    for (int t = 0; t < Tt; t++) { float e = expf(sm[t*RED + tid] - mx); sm[t*RED + tid] = e; s += e; }
    float inv = 1.f / s;
    for (int t = 0; t < Tt; t++) sm[t*RED + tid] *= inv;
  }
  __syncthreads();

  size_t pbase = ((size_t)(n*Bsz + b)) * CR;
  for (int idx = tid; idx < CR; idx += 256) {
    int c = idx >> 4, r = idx & 15;
    float acc = 0.f;
#pragma unroll
    for (int t = 0; t < Tt; t++) acc += sp[t*Cch + c] * sm[t*RED + r];
    __nv_bfloat16 hv = __float2bfloat16(acc);
    g_pooled_hi[pbase + idx] = hv;
    g_pooled_lo[pbase + idx] = __float2bfloat16(acc - __bfloat162float(hv));
  }

  {
    int c = tid;
    float mx = -INFINITY;
#pragma unroll
    for (int t = 0; t < Tt; t++) mx = fmaxf(mx, sp[t*Cch + c]);
    g_pmax[(size_t)(n*Bsz + b)*Cch + c] = mx;
  }
}

// ========== K3: HMMA GEMM  feat = pmax + leaky(pooled @ Wout) ==========
// block: bin n, 64-col tile of Wout. 256 thr = 8 warps: 4 in M (32) x 2 in N (32).
#define WKP 40   // smem k-pitch in halves (conflict-free)
__global__ void __launch_bounds__(256) k_gemmW(const float* __restrict__ Wout) {
  __shared__ __align__(16) __nv_bfloat16 sAhi[128*WKP], sAlo[128*WKP];
  __shared__ __align__(16) __nv_bfloat16 sBhi[64*WKP],  sBlo[64*WKP];

  int n = blockIdx.y;
  int col0 = blockIdx.x * 64;
  int tid = threadIdx.x;
  int wid = tid >> 5, lane = tid & 31;
  int m0 = (wid >> 1) * 32;
  int n0 = (wid & 1) * 32;
  int gr = lane >> 2, tc = lane & 3;

  const __nv_bfloat16* Ahi = g_pooled_hi + (size_t)n*Bsz*CR;
  const __nv_bfloat16* Alo = g_pooled_lo + (size_t)n*Bsz*CR;
  const float* Bg = Wout + (size_t)n*CR*Cch;

  float acc[2][4][4];
#pragma unroll
  for (int i = 0; i < 2; i++)
#pragma unroll
    for (int j = 0; j < 4; j++)
#pragma unroll
      for (int q = 0; q < 4; q++) acc[i][j][q] = 0.f;

  int colB = tid & 63;
  int kB = tid >> 6;   // 0..3

  for (int k0 = 0; k0 < CR; k0 += 32) {
#pragma unroll
    for (int i = 0; i < 16; i++) {
      int idx = i*256 + tid;
      int m = idx >> 5, k = idx & 31;
      sAhi[m*WKP + k] = Ahi[(size_t)m*CR + k0 + k];
      sAlo[m*WKP + k] = Alo[(size_t)m*CR + k0 + k];
    }
#pragma unroll
    for (int i = 0; i < 8; i++) {
      int k = kB + i*4;
      float v = Bg[(size_t)(k0 + k)*Cch + col0 + colB];
      __nv_bfloat16 hv = __float2bfloat16(v);
      sBhi[colB*WKP + k] = hv;
      sBlo[colB*WKP + k] = __float2bfloat16(v - __bfloat162float(hv));
    }
    __syncthreads();

#pragma unroll
    for (int ks = 0; ks < 32; ks += 16) {
      uint32_t ahi[2][4], alo[2][4], bhi[4][2], blo[4][2];
#pragma unroll
      for (int mt = 0; mt < 2; mt++) {
        int ba = (m0 + mt*16 + gr)*WKP + ks + tc*2;
        ahi[mt][0] = *(const uint32_t*)(sAhi + ba);
        ahi[mt][1] = *(const uint32_t*)(sAhi + ba + 8*WKP);
        ahi[mt][2] = *(const uint32_t*)(sAhi + ba + 8);
        ahi[mt][3] = *(const uint32_t*)(sAhi + ba + 8*WKP + 8);
        alo[mt][0] = *(const uint32_t*)(sAlo + ba);
        alo[mt][1] = *(const uint32_t*)(sAlo + ba + 8*WKP);
        alo[mt][2] = *(const uint32_t*)(sAlo + ba + 8);
        alo[mt][3] = *(const uint32_t*)(sAlo + ba + 8*WKP + 8);
      }
#pragma unroll
      for (int nt = 0; nt < 4; nt++) {
        int bb = (n0 + nt*8 + gr)*WKP + ks + tc*2;
        bhi[nt][0] = *(const uint32_t*)(sBhi + bb);
        bhi[nt][1] = *(const uint32_t*)(sBhi + bb + 8);
        blo[nt][0] = *(const uint32_t*)(sBlo + bb);
        blo[nt][1] = *(const uint32_t*)(sBlo + bb + 8);
      }
#pragma unroll
      for (int mt = 0; mt < 2; mt++)
#pragma unroll
        for (int nt = 0; nt < 4; nt++) {
          mma_bf16(acc[mt][nt], ahi[mt], bhi[nt]);
          mma_bf16(acc[mt][nt], ahi[mt], blo[nt]);
          mma_bf16(acc[mt][nt], alo[mt], bhi[nt]);
        }
    }
    __syncthreads();
  }

#pragma unroll
  for (int mt = 0; mt < 2; mt++)
#pragma unroll
    for (int nt = 0; nt < 4; nt++) {
      int row = m0 + mt*16 + gr;
      int c = col0 + n0 + nt*8 + tc*2;
#pragma unroll
      for (int h = 0; h < 2; h++) {
        int rr = row + h*8;
        float v0 = acc[mt][nt][h*2], v1 = acc[mt][nt][h*2+1];
        float l0 = v0 >= 0.f ? v0 : 0.01f*v0;
        float l1 = v1 >= 0.f ? v1 : 0.01f*v1;
        size_t a = (size_t)(n*Bsz + rr)*Cch + c;
        float2 pm = *(const float2*)&g_pmax[a];
        float2 o = make_float2(pm.x + l0, pm.y + l1);
        *(float2*)&g_feat[a] = o;
      }
    }
}

// ========== K4: scalar f32x2 GEMM  outputs = feat @ FForward ==========
__global__ void __launch_bounds__(256) k_gemmF(const float* __restrict__ Bmat,
                                               float* __restrict__ dout) {
  int n = blockIdx.y;
  int col0 = blockIdx.x * 64;
  __shared__ __align__(16) float sA[32*132];
  __shared__ __align__(16) float sB[32*64];
  int tid = threadIdx.x;
  int tx = tid & 15, ty = tid >> 4;

  const float* Ag = g_feat + (size_t)n*Bsz*OUTC;
  const float* Bg = Bmat + (size_t)n*OUTC*Cch;

  unsigned long long acc[4][4];
#pragma unroll
  for (int i = 0; i < 4; i++)
#pragma unroll
    for (int j = 0; j < 4; j++) acc[i][j] = 0ull;

  int rA = tid >> 5, kA = tid & 31;
  int cB = tid & 63, kB = tid >> 6;

  for (int k0 = 0; k0 < OUTC; k0 += 32) {
#pragma unroll
    for (int i = 0; i < 16; i++)
      sA[kA*132 + rA + i*8] = Ag[(size_t)(rA + i*8)*OUTC + (k0 + kA)];
#pragma unroll
    for (int i = 0; i < 8; i++)
      sB[(kB + i*4)*64 + cB] = Bg[(size_t)(k0 + kB + i*4)*Cch + col0 + cB];
    __syncthreads();

#pragma unroll
    for (int kk = 0; kk < 32; kk++) {
      const float* ap = sA + kk*132 + ty*8;
      ulonglong2 a01 = *(const ulonglong2*)ap;
      ulonglong2 a23 = *(const ulonglong2*)(ap + 4);
      const float* bp = sB + kk*64 + tx;
#pragma unroll
      for (int j = 0; j < 4; j++) {
        float bv = bp[j*16];
        unsigned long long bb = pack2(bv, bv);
        acc[0][j] = fma2(a01.x, bb, acc[0][j]);
        acc[1][j] = fma2(a01.y, bb, acc[1][j]);
        acc[2][j] = fma2(a23.x, bb, acc[2][j]);
        acc[3][j] = fma2(a23.y, bb, acc[3][j]);
      }
    }
    __syncthreads();
  }

#pragma unroll
  for (int pi = 0; pi < 4; pi++) {
    int row = ty*8 + pi*2;
#pragma unroll
    for (int j = 0; j < 4; j++) {
      int c = col0 + tx + j*16;
      float2 v = unpack2(acc[pi][j]);
      g_outputs[(size_t)(n*Bsz + row)*OUTC + c]     = v.x;
      g_outputs[(size_t)(n*Bsz + row + 1)*OUTC + c] = v.y;
      dout[((size_t)row*NB + n)*OUTC + c]       = v.x;
      dout[((size_t)(row+1)*NB + n)*OUTC + c]   = v.y;
    }
  }
}

// ========== K5: BatchNorm stats ==========
__global__ void k_bnstats(const float* __restrict__ gamma,
                          const float* __restrict__ beta) {
  int n = blockIdx.x;
  int o = threadIdx.x;
  const float* base = g_outputs + (size_t)n*Bsz*OUTC + o;
  float s = 0.f;
  for (int b = 0; b < Bsz; b++) s += base[(size_t)b*OUTC];
  float mean = s * (1.f/Bsz);
  float v = 0.f;
  for (int b = 0; b < Bsz; b++) { float d = base[(size_t)b*OUTC] - mean; v += d*d; }
  v *= (1.f/Bsz);
  float sc = gamma[n*OUTC + o] / sqrtf(v + 1e-5f);
  g_scale[n*OUTC + o] = sc;
  g_shift[n*OUTC + o] = beta[n*OUTC + o] - mean * sc;
}

// ========== K6: apply BN + L2-normalize, emit bf16 hi/lo split ==========
__global__ void __launch_bounds__(256) k_bnn() {
  int b = blockIdx.x, n = blockIdx.y;
  int o = threadIdx.x;
  float v = g_scale[n*OUTC + o] * g_outputs[(size_t)(n*Bsz + b)*OUTC + o] + g_shift[n*OUTC + o];
  float ss = v * v;
#pragma unroll
  for (int off = 16; off; off >>= 1) ss += __shfl_down_sync(0xffffffffu, ss, off);
  __shared__ float red[8];
  __shared__ float invn;
  if ((o & 31) == 0) red[o >> 5] = ss;
  __syncthreads();
  if (o == 0) {
    float s = 0.f;
#pragma unroll
    for (int i = 0; i < 8; i++) s += red[i];
    invn = 1.f / fmaxf(sqrtf(s), 1e-12f);
  }
  __syncthreads();
  float bv = v * invn;
  __nv_bfloat16 hv = __float2bfloat16(bv);
  size_t idx = (size_t)(n*Bsz + b)*OUTC + o;
  g_bnn_hi[idx] = hv;
  g_bnn_lo[idx] = __float2bfloat16(bv - __bfloat162float(hv));
}

// ========== K7: HMMA logits GEMM with fused classifier column norm ==========
// block: bin n, 128-col class tile. 8 warps: 2 in M (64) x 4 in N (32).
#define LKP 40
__global__ void __launch_bounds__(256) k_logits_mma(const float* __restrict__ fc,
                                                    float* __restrict__ out) {
  __shared__ __align__(16) __nv_bfloat16 sAhi[128*LKP], sAlo[128*LKP];
  __shared__ __align__(16) __nv_bfloat16 sBhi[128*LKP], sBlo[128*LKP];
  __shared__ float sred[256];
  __shared__ float sinv[128];

  int n = blockIdx.y;
  int col0 = blockIdx.x * 128;
  int tid = threadIdx.x;
  int wid = tid >> 5, lane = tid & 31;
  int m0 = (wid >> 2) * 64;
  int n0 = (wid & 3) * 32;
  int gr = lane >> 2, tc = lane & 3;

  const __nv_bfloat16* Ahi = g_bnn_hi + (size_t)n*Bsz*OUTC;
  const __nv_bfloat16* Alo = g_bnn_lo + (size_t)n*Bsz*OUTC;
  const float* Bg = fc + (size_t)n*OUTC*KCLS;

  float acc[4][4][4];
#pragma unroll
  for (int i = 0; i < 4; i++)
#pragma unroll
    for (int j = 0; j < 4; j++)
#pragma unroll
      for (int q = 0; q < 4; q++) acc[i][j][q] = 0.f;

  int colB = tid & 127;
  int kB = tid >> 7;   // 0/1
  int gc = col0 + colB;
  bool cok = gc < KCLS;
  float ss = 0.f;

  for (int ch = 0; ch < 8; ch++) {
    int k0 = ch * 32;
#pragma unroll
    for (int i = 0; i < 16; i++) {
      int idx = i*256 + tid;
      int m = idx >> 5, k = idx & 31;
      sAhi[m*LKP + k] = Ahi[(size_t)m*OUTC + k0 + k];
      sAlo[m*LKP + k] = Alo[(size_t)m*OUTC + k0 + k];
    }
#pragma unroll
    for (int i = 0; i < 16; i++) {
      int k = kB + i*2;
      float v = cok ? Bg[(size_t)(k0 + k)*KCLS + gc] : 0.f;
      ss += v * v;
      __nv_bfloat16 hv = __float2bfloat16(v);
      sBhi[colB*LKP + k] = hv;
      sBlo[colB*LKP + k] = __float2bfloat16(v - __bfloat162float(hv));
    }
    __syncthreads();

#pragma unroll
    for (int ks = 0; ks < 32; ks += 16) {
      uint32_t ahi[4][4], alo[4][4], bhi[4][2], blo[4][2];
#pragma unroll
      for (int mt = 0; mt < 4; mt++) {
        int ba = (m0 + mt*16 + gr)*LKP + ks + tc*2;
        ahi[mt][0] = *(const uint32_t*)(sAhi + ba);
        ahi[mt][1] = *(const uint32_t*)(sAhi + ba + 8*LKP);
        ahi[mt][2] = *(const uint32_t*)(sAhi + ba + 8);
        ahi[mt][3] = *(const uint32_t*)(sAhi + ba + 8*LKP + 8);
        alo[mt][0] = *(const uint32_t*)(sAlo + ba);
        alo[mt][1] = *(const uint32_t*)(sAlo + ba + 8*LKP);
        alo[mt][2] = *(const uint32_t*)(sAlo + ba + 8);
        alo[mt][3] = *(const uint32_t*)(sAlo + ba + 8*LKP + 8);
      }
#pragma unroll
      for (int nt = 0; nt < 4; nt++) {
        int bb = (n0 + nt*8 + gr)*LKP + ks + tc*2;
        bhi[nt][0] = *(const uint32_t*)(sBhi + bb);
        bhi[nt][1] = *(const uint32_t*)(sBhi + bb + 8);
        blo[nt][0] = *(const uint32_t*)(sBlo + bb);
        blo[nt][1] = *(const uint32_t*)(sBlo + bb + 8);
      }
#pragma unroll
      for (int mt = 0; mt < 4; mt++)
#pragma unroll
        for (int nt = 0; nt < 4; nt++) {
          mma_bf16(acc[mt][nt], ahi[mt], bhi[nt]);
          mma_bf16(acc[mt][nt], ahi[mt], blo[nt]);
          mma_bf16(acc[mt][nt], alo[mt], bhi[nt]);
        }
    }
    __syncthreads();
  }

  sred[tid] = ss;
  __syncthreads();
  if (tid < 128) sinv[tid] = 1.f / fmaxf(sqrtf(sred[tid] + sred[tid + 128]), 1e-12f);
  __syncthreads();

#pragma unroll
  for (int mt = 0; mt < 4; mt++)
#pragma unroll
    for (int nt = 0; nt < 4; nt++) {
      int row = m0 + mt*16 + gr;
      int cl = n0 + nt*8 + tc*2;
      int c = col0 + cl;
      if (c < KCLS) {
        float i0 = sinv[cl], i1 = sinv[cl + 1];
        float2 v0 = make_float2(acc[mt][nt][0]*i0, acc[mt][nt][1]*i1);
        float2 v1 = make_float2(acc[mt][nt][2]*i0, acc[mt][nt][3]*i1);
        *(float2*)&out[((size_t)row*NB + n)*KCLS + c] = v0;
        *(float2*)&out[((size_t)(row+8)*NB + n)*KCLS + c] = v1;
      }
    }
}

// ========== launch ==========
extern "C" void kernel_launch(void* const* d_in, const int* in_sizes, int n_in,
                              void* d_out, int out_size) {
  const float* x        = (const float*)d_in[0];
  const float* Wmask    = (const float*)d_in[1];
  const float* Wout     = (const float*)d_in[2];
  const float* FForward = (const float*)d_in[3];
  const float* gamma    = (const float*)d_in[4];
  const float* beta     = (const float*)d_in[5];
  const float* fc1d     = (const float*)d_in[6];
  float* out        = (float*)d_out;
  float* out_logits = out + (size_t)Bsz*NB*OUTC;

  k_strip  <<<dim3(Bsz*Tt, Cch/32), 1024>>>(x);
  k_gmpa   <<<dim3(Bsz, NB), 256>>>(Wmask);
  k_gemmW  <<<dim3(4, NB), 256>>>(Wout);
  k_gemmF  <<<dim3(4, NB), 256>>>(FForward, out);
  k_bnstats<<<NB, OUTC>>>(gamma, beta);
  k_bnn    <<<dim3(Bsz, NB), 256>>>();
  k_logits_mma<<<dim3((KCLS + 127)/128, NB), 256>>>(fc1d, out_logits);
}

// round 4
// speedup vs baseline: 1.6326x; 1.3658x over previous
#include <cuda_runtime.h>
#include <cuda_fp16.h>
#include <math.h>
#include <stdint.h>

#define Bsz  128
#define Cch  256
#define Tt   30
#define Hh   16
#define Ww   11
#define NB   31
#define RED  16
#define OUTC 256
#define KCLS 10000
#define CR   4096   // Cch*RED

// -------- scratch (device globals) --------
__device__ float g_p[(size_t)NB*Bsz*Tt*Cch];       // [n][B][T][C]
__device__ float g_pmax[NB*Bsz*Cch];
__device__ __half g_pooled_h[(size_t)NB*Bsz*CR];   // fp16 hi
__device__ __half g_pooled_l[(size_t)NB*Bsz*CR];   // fp16 lo (residual)
__device__ float g_feat[NB*Bsz*Cch];
__device__ float g_outputs[NB*Bsz*OUTC];
__device__ float g_scale[NB*OUTC];
__device__ float g_shift[NB*OUTC];
__device__ __half g_bnn_h[NB*Bsz*OUTC];
__device__ __half g_bnn_l[NB*Bsz*OUTC];

// -------- packed fp32x2 helpers --------
__device__ __forceinline__ unsigned long long pack2(float lo, float hi) {
  unsigned long long r;
  asm("mov.b64 %0, {%1, %2};" : "=l"(r) : "f"(lo), "f"(hi));
  return r;
}
__device__ __forceinline__ unsigned long long fma2(unsigned long long a,
                                                   unsigned long long b,
                                                   unsigned long long c) {
  unsigned long long d;
  asm("fma.rn.f32x2 %0, %1, %2, %3;" : "=l"(d) : "l"(a), "l"(b), "l"(c));
  return d;
}
__device__ __forceinline__ float2 unpack2(unsigned long long v) {
  float lo, hi;
  asm("mov.b64 {%0, %1}, %2;" : "=f"(lo), "=f"(hi) : "l"(v));
  return make_float2(lo, hi);
}

// -------- warp-level fp16 MMA (m16n8k16), fp32 accumulate --------
__device__ __forceinline__ void mma_f16(float* d, const uint32_t* a, const uint32_t* b) {
  asm volatile("mma.sync.aligned.m16n8k16.row.col.f32.f16.f16.f32 "
               "{%0,%1,%2,%3}, {%4,%5,%6,%7}, {%8,%9}, {%0,%1,%2,%3};"
               : "+f"(d[0]), "+f"(d[1]), "+f"(d[2]), "+f"(d[3])
               : "r"(a[0]), "r"(a[1]), "r"(a[2]), "r"(a[3]),
                 "r"(b[0]), "r"(b[1]));
}
__device__ __forceinline__ void ldmx4(uint32_t* r, uint32_t addr) {
  asm volatile("ldmatrix.sync.aligned.m8n8.x4.shared.b16 {%0,%1,%2,%3}, [%4];"
               : "=r"(r[0]), "=r"(r[1]), "=r"(r[2]), "=r"(r[3]) : "r"(addr));
}
__device__ __forceinline__ uint32_t smem_u32(const void* p) {
  return (uint32_t)__cvta_generic_to_shared(p);
}

// ========== K1: horizontal strip pooling (mean+max per strip) ==========
__global__ void __launch_bounds__(1024) k_strip(const float* __restrict__ x) {
  int bt = blockIdx.x;
  int b = bt / Tt, t = bt % Tt;
  int warp = threadIdx.x >> 5;
  int lane = threadIdx.x & 31;
  int c = blockIdx.y * 32 + warp;

  __shared__ float sm[NB][33];

  const float* base = x + (((size_t)(b*Cch + c)*Tt + t) * Hh) * Ww;
  float s = 0.f, m = -INFINITY;
  if (lane < 16) {
    const float* row = base + lane * Ww;
#pragma unroll
    for (int w = 0; w < Ww; w++) { float v = row[w]; s += v; m = fmaxf(m, v); }
  }
  if (lane < 16) sm[15 + lane][warp] = s * (1.f/11.f) + m;
  float s2 = s + __shfl_down_sync(0xffffffffu, s, 1);
  float m2 = fmaxf(m, __shfl_down_sync(0xffffffffu, m, 1));
  if (lane < 16 && (lane & 1) == 0) sm[7 + (lane>>1)][warp] = s2*(1.f/22.f) + m2;
  float s4 = s2 + __shfl_down_sync(0xffffffffu, s2, 2);
  float m4 = fmaxf(m2, __shfl_down_sync(0xffffffffu, m2, 2));
  if (lane < 16 && (lane & 3) == 0) sm[3 + (lane>>2)][warp] = s4*(1.f/44.f) + m4;
  float s8 = s4 + __shfl_down_sync(0xffffffffu, s4, 4);
  float m8 = fmaxf(m4, __shfl_down_sync(0xffffffffu, m4, 4));
  if (lane < 16 && (lane & 7) == 0) sm[1 + (lane>>3)][warp] = s8*(1.f/88.f) + m8;
  float s16 = s8 + __shfl_down_sync(0xffffffffu, s8, 8);
  float m16 = fmaxf(m8, __shfl_down_sync(0xffffffffu, m8, 8));
  if (lane == 0) sm[0][warp] = s16*(1.f/176.f) + m16;
  __syncthreads();

  int tid = threadIdx.x;
  if (tid < NB * 32) {
    int bin = tid >> 5, col = tid & 31;
    int cc = blockIdx.y * 32 + col;
    g_p[(((size_t)bin*Bsz + b)*Tt + t)*Cch + cc] = sm[bin][col];
  }
}

// ========== K2: per (n,b) GMPA front (emits pooled as fp16 hi/lo) ==========
__global__ void __launch_bounds__(256) k_gmpa(const float* __restrict__ Wmask) {
  int b = blockIdx.x, n = blockIdx.y;
  __shared__ float sp[Tt*Cch];
  __shared__ float swm[Cch*RED];
  __shared__ float sm[Tt*RED];
  int tid = threadIdx.x;

  const float* pg = g_p + ((size_t)(n*Bsz + b)) * (Tt*Cch);
  for (int i = tid; i < Tt*Cch; i += 256) sp[i] = pg[i];
  for (int i = tid; i < Cch*RED; i += 256) swm[i] = Wmask[(size_t)n*Cch*RED + i];
  __syncthreads();

  for (int idx = tid; idx < Tt*RED; idx += 256) {
    int t = idx / RED, r = idx % RED;
    const float* pr = sp + t*Cch;
    float acc = 0.f;
#pragma unroll 8
    for (int c = 0; c < Cch; c++) acc += pr[c] * swm[c*RED + r];
    sm[idx] = acc;
  }
  __syncthreads();

  if (tid < RED) {
    float mx = -INFINITY;
    for (int t = 0; t < Tt; t++) mx = fmaxf(mx, sm[t*RED + tid]);
    float s = 0.f;
    for (int t = 0; t < Tt; t++) { float e = expf(sm[t*RED + tid] - mx); sm[t*RED + tid] = e; s += e; }
    float inv = 1.f / s;
    for (int t = 0; t < Tt; t++) sm[t*RED + tid] *= inv;
  }
  __syncthreads();

  size_t pbase = ((size_t)(n*Bsz + b)) * CR;
  for (int idx = tid; idx < CR; idx += 256) {
    int c = idx >> 4, r = idx & 15;
    float acc = 0.f;
#pragma unroll
    for (int t = 0; t < Tt; t++) acc += sp[t*Cch + c] * sm[t*RED + r];
    __half hv = __float2half_rn(acc);
    g_pooled_h[pbase + idx] = hv;
    g_pooled_l[pbase + idx] = __float2half_rn(acc - __half2float(hv));
  }

  {
    int c = tid;
    float mx = -INFINITY;
#pragma unroll
    for (int t = 0; t < Tt; t++) mx = fmaxf(mx, sp[t*Cch + c]);
    g_pmax[(size_t)(n*Bsz + b)*Cch + c] = mx;
  }
}

// ========== K3: HMMA fp16 2-term  feat = pmax + leaky(pooled @ Wout) ==========
// 256 thr, 8 warps: (wid>>1)=M-quad (32 rows), (wid&1)=N-half (32 cols).
#define WKP 40
#define WNCH (CR/32)
__global__ void __launch_bounds__(256, 2) k_gemmW(const float* __restrict__ Wout) {
  __shared__ __align__(16) __half sAh[128*WKP], sAl[128*WKP];
  __shared__ __align__(16) __half sBh[64*WKP];

  int n = blockIdx.y;
  int col0 = blockIdx.x * 64;
  int tid = threadIdx.x;
  int wid = tid >> 5, lane = tid & 31;
  int mrow0 = (wid >> 1) * 32;
  int ncol0 = (wid & 1) * 32;
  int gr = lane >> 2, tc = lane & 3;

  const __half* Ah = g_pooled_h + (size_t)n*Bsz*CR;
  const __half* Al = g_pooled_l + (size_t)n*Bsz*CR;
  const float* Bg = Wout + (size_t)n*CR*Cch;

  int mA = tid >> 1, segA = tid & 1;
  int colB = tid & 63, kB = tid >> 6;

  float acc[2][4][4];
#pragma unroll
  for (int i = 0; i < 2; i++)
#pragma unroll
    for (int j = 0; j < 4; j++)
#pragma unroll
      for (int q = 0; q < 4; q++) acc[i][j][q] = 0.f;

  uint32_t uAh = smem_u32(sAh), uAl = smem_u32(sAl), uBh = smem_u32(sBh);

  uint4 rAh0, rAh1, rAl0, rAl1;
  float rB[8];
  {
    const uint4* pAh = (const uint4*)(Ah + (size_t)mA*CR + segA*16);
    rAh0 = pAh[0]; rAh1 = pAh[1];
    const uint4* pAl = (const uint4*)(Al + (size_t)mA*CR + segA*16);
    rAl0 = pAl[0]; rAl1 = pAl[1];
#pragma unroll
    for (int i = 0; i < 8; i++)
      rB[i] = Bg[(size_t)(kB + i*4)*Cch + col0 + colB];
  }

  for (int ch = 0; ch < WNCH; ch++) {
    // stage to smem
    *(uint4*)(sAh + mA*WKP + segA*16)     = rAh0;
    *(uint4*)(sAh + mA*WKP + segA*16 + 8) = rAh1;
    *(uint4*)(sAl + mA*WKP + segA*16)     = rAl0;
    *(uint4*)(sAl + mA*WKP + segA*16 + 8) = rAl1;
#pragma unroll
    for (int i = 0; i < 8; i++)
      sBh[colB*WKP + kB + i*4] = __float2half_rn(rB[i]);
    __syncthreads();

    // prefetch next chunk (overlaps MMA below)
    if (ch + 1 < WNCH) {
      int k0 = (ch + 1) * 32;
      const uint4* pAh = (const uint4*)(Ah + (size_t)mA*CR + k0 + segA*16);
      rAh0 = pAh[0]; rAh1 = pAh[1];
      const uint4* pAl = (const uint4*)(Al + (size_t)mA*CR + k0 + segA*16);
      rAl0 = pAl[0]; rAl1 = pAl[1];
#pragma unroll
      for (int i = 0; i < 8; i++)
        rB[i] = Bg[(size_t)(k0 + kB + i*4)*Cch + col0 + colB];
    }

#pragma unroll
    for (int ks = 0; ks < 32; ks += 16) {
      uint32_t ah[2][4], al[2][4], bh[2][4];
      int arow = lane & 15, asel = (lane >> 4) * 8;
#pragma unroll
      for (int mt = 0; mt < 2; mt++) {
        uint32_t off = ((mrow0 + mt*16 + arow)*WKP + ks + asel) * 2;
        ldmx4(ah[mt], uAh + off);
        ldmx4(al[mt], uAl + off);
      }
      {
        int j = lane >> 3;
        int brow = ((j >> 1) << 3) + (lane & 7);
        int bkof = (j & 1) << 3;
        ldmx4(bh[0], uBh + ((ncol0 + brow)*WKP + ks + bkof) * 2);
        ldmx4(bh[1], uBh + ((ncol0 + 16 + brow)*WKP + ks + bkof) * 2);
      }
#pragma unroll
      for (int mt = 0; mt < 2; mt++)
#pragma unroll
        for (int g = 0; g < 2; g++)
#pragma unroll
          for (int h = 0; h < 2; h++) {
            mma_f16(acc[mt][g*2 + h], ah[mt], &bh[g][h*2]);
            mma_f16(acc[mt][g*2 + h], al[mt], &bh[g][h*2]);
          }
    }
    __syncthreads();
  }

#pragma unroll
  for (int mt = 0; mt < 2; mt++)
#pragma unroll
    for (int nt = 0; nt < 4; nt++) {
      int row = mrow0 + mt*16 + gr;
      int c = col0 + ncol0 + nt*8 + tc*2;
#pragma unroll
      for (int h = 0; h < 2; h++) {
        int rr = row + h*8;
        float v0 = acc[mt][nt][h*2], v1 = acc[mt][nt][h*2+1];
        float l0 = v0 >= 0.f ? v0 : 0.01f*v0;
        float l1 = v1 >= 0.f ? v1 : 0.01f*v1;
        size_t a = (size_t)(n*Bsz + rr)*Cch + c;
        float2 pm = *(const float2*)&g_pmax[a];
        *(float2*)&g_feat[a] = make_float2(pm.x + l0, pm.y + l1);
      }
    }
}

// ========== K4: scalar f32x2 GEMM  outputs = feat @ FForward (exact fp32) ==========
__global__ void __launch_bounds__(256) k_gemmF(const float* __restrict__ Bmat,
                                               float* __restrict__ dout) {
  int n = blockIdx.y;
  int col0 = blockIdx.x * 64;
  __shared__ __align__(16) float sA[32*132];
  __shared__ __align__(16) float sB[32*64];
  int tid = threadIdx.x;
  int tx = tid & 15, ty = tid >> 4;

  const float* Ag = g_feat + (size_t)n*Bsz*OUTC;
  const float* Bg = Bmat + (size_t)n*OUTC*Cch;

  unsigned long long acc[4][4];
#pragma unroll
  for (int i = 0; i < 4; i++)
#pragma unroll
    for (int j = 0; j < 4; j++) acc[i][j] = 0ull;

  int rA = tid >> 5, kA = tid & 31;
  int cB = tid & 63, kB = tid >> 6;

  for (int k0 = 0; k0 < OUTC; k0 += 32) {
#pragma unroll
    for (int i = 0; i < 16; i++)
      sA[kA*132 + rA + i*8] = Ag[(size_t)(rA + i*8)*OUTC + (k0 + kA)];
#pragma unroll
    for (int i = 0; i < 8; i++)
      sB[(kB + i*4)*64 + cB] = Bg[(size_t)(k0 + kB + i*4)*Cch + col0 + cB];
    __syncthreads();

#pragma unroll
    for (int kk = 0; kk < 32; kk++) {
      const float* ap = sA + kk*132 + ty*8;
      ulonglong2 a01 = *(const ulonglong2*)ap;
      ulonglong2 a23 = *(const ulonglong2*)(ap + 4);
      const float* bp = sB + kk*64 + tx;
#pragma unroll
      for (int j = 0; j < 4; j++) {
        float bv = bp[j*16];
        unsigned long long bb = pack2(bv, bv);
        acc[0][j] = fma2(a01.x, bb, acc[0][j]);
        acc[1][j] = fma2(a01.y, bb, acc[1][j]);
        acc[2][j] = fma2(a23.x, bb, acc[2][j]);
        acc[3][j] = fma2(a23.y, bb, acc[3][j]);
      }
    }
    __syncthreads();
  }

#pragma unroll
  for (int pi = 0; pi < 4; pi++) {
    int row = ty*8 + pi*2;
#pragma unroll
    for (int j = 0; j < 4; j++) {
      int c = col0 + tx + j*16;
      float2 v = unpack2(acc[pi][j]);
      g_outputs[(size_t)(n*Bsz + row)*OUTC + c]     = v.x;
      g_outputs[(size_t)(n*Bsz + row + 1)*OUTC + c] = v.y;
      dout[((size_t)row*NB + n)*OUTC + c]       = v.x;
      dout[((size_t)(row+1)*NB + n)*OUTC + c]   = v.y;
    }
  }
}

// ========== K5: BatchNorm stats ==========
__global__ void k_bnstats(const float* __restrict__ gamma,
                          const float* __restrict__ beta) {
  int n = blockIdx.x;
  int o = threadIdx.x;
  const float* base = g_outputs + (size_t)n*Bsz*OUTC + o;
  float s = 0.f;
  for (int b = 0; b < Bsz; b++) s += base[(size_t)b*OUTC];
  float mean = s * (1.f/Bsz);
  float v = 0.f;
  for (int b = 0; b < Bsz; b++) { float d = base[(size_t)b*OUTC] - mean; v += d*d; }
  v *= (1.f/Bsz);
  float sc = gamma[n*OUTC + o] / sqrtf(v + 1e-5f);
  g_scale[n*OUTC + o] = sc;
  g_shift[n*OUTC + o] = beta[n*OUTC + o] - mean * sc;
}

// ========== K6: apply BN + L2-normalize, emit fp16 hi/lo ==========
__global__ void __launch_bounds__(256) k_bnn() {
  int b = blockIdx.x, n = blockIdx.y;
  int o = threadIdx.x;
  float v = g_scale[n*OUTC + o] * g_outputs[(size_t)(n*Bsz + b)*OUTC + o] + g_shift[n*OUTC + o];
  float ss = v * v;
#pragma unroll
  for (int off = 16; off; off >>= 1) ss += __shfl_down_sync(0xffffffffu, ss, off);
  __shared__ float red[8];
  __shared__ float invn;
  if ((o & 31) == 0) red[o >> 5] = ss;
  __syncthreads();
  if (o == 0) {
    float s = 0.f;
#pragma unroll
    for (int i = 0; i < 8; i++) s += red[i];
    invn = 1.f / fmaxf(sqrtf(s), 1e-12f);
  }
  __syncthreads();
  float bv = v * invn;
  __half hv = __float2half_rn(bv);
  size_t idx = (size_t)(n*Bsz + b)*OUTC + o;
  g_bnn_h[idx] = hv;
  g_bnn_l[idx] = __float2half_rn(bv - __half2float(hv));
}

// ========== K7: HMMA fp16 2-term logits GEMM, fused column norm ==========
// 512 thr, 16 warps: (wid>>2)=M-quad (32 rows), (wid&3)=N-quad (32 cols).
#define LKP 40
__global__ void __launch_bounds__(512, 1) k_logits_mma(const float* __restrict__ fc,
                                                       float* __restrict__ out) {
  __shared__ __align__(16) __half sAh[128*LKP], sAl[128*LKP];
  __shared__ __align__(16) __half sBh[128*LKP];
  __shared__ float sred[512];
  __shared__ float sinv[128];

  int n = blockIdx.y;
  int col0 = blockIdx.x * 128;
  int tid = threadIdx.x;
  int wid = tid >> 5, lane = tid & 31;
  int mrow0 = (wid >> 2) * 32;
  int ncol0 = (wid & 3) * 32;
  int gr = lane >> 2, tc = lane & 3;

  const __half* Ah = g_bnn_h + (size_t)n*Bsz*OUTC;
  const __half* Al = g_bnn_l + (size_t)n*Bsz*OUTC;
  const float* Bg = fc + (size_t)n*OUTC*KCLS;

  int mA = tid >> 2, segA = tid & 3;
  int colB = tid & 127, kB = tid >> 7;
  int gc = col0 + colB;
  bool cok = gc < KCLS;

  float acc[2][4][4];
#pragma unroll
  for (int i = 0; i < 2; i++)
#pragma unroll
    for (int j = 0; j < 4; j++)
#pragma unroll
      for (int q = 0; q < 4; q++) acc[i][j][q] = 0.f;

  uint32_t uAh = smem_u32(sAh), uAl = smem_u32(sAl), uBh = smem_u32(sBh);

  uint4 rAh, rAl;
  float rB[8];
  {
    rAh = *(const uint4*)(Ah + (size_t)mA*OUTC + segA*8);
    rAl = *(const uint4*)(Al + (size_t)mA*OUTC + segA*8);
#pragma unroll
    for (int i = 0; i < 8; i++)
      rB[i] = cok ? Bg[(size_t)(kB + i*4)*KCLS + gc] : 0.f;
  }

  float ss = 0.f;

  for (int ch = 0; ch < 8; ch++) {
    *(uint4*)(sAh + mA*LKP + segA*8) = rAh;
    *(uint4*)(sAl + mA*LKP + segA*8) = rAl;
#pragma unroll
    for (int i = 0; i < 8; i++) {
      float v = rB[i];
      ss += v * v;
      sBh[colB*LKP + kB + i*4] = __float2half_rn(v);
    }
    __syncthreads();

    if (ch + 1 < 8) {
      int k0 = (ch + 1) * 32;
      rAh = *(const uint4*)(Ah + (size_t)mA*OUTC + k0 + segA*8);
      rAl = *(const uint4*)(Al + (size_t)mA*OUTC + k0 + segA*8);
#pragma unroll
      for (int i = 0; i < 8; i++)
        rB[i] = cok ? Bg[(size_t)(k0 + kB + i*4)*KCLS + gc] : 0.f;
    }

#pragma unroll
    for (int ks = 0; ks < 32; ks += 16) {
      uint32_t ah[2][4], al[2][4], bh[2][4];
      int arow = lane & 15, asel = (lane >> 4) * 8;
#pragma unroll
      for (int mt = 0; mt < 2; mt++) {
        uint32_t off = ((mrow0 + mt*16 + arow)*LKP + ks + asel) * 2;
        ldmx4(ah[mt], uAh + off);
        ldmx4(al[mt], uAl + off);
      }
      {
        int j = lane >> 3;
        int brow = ((j >> 1) << 3) + (lane & 7);
        int bkof = (j & 1) << 3;
        ldmx4(bh[0], uBh + ((ncol0 + brow)*LKP + ks + bkof) * 2);
        ldmx4(bh[1], uBh + ((ncol0 + 16 + brow)*LKP + ks + bkof) * 2);
      }
#pragma unroll
      for (int mt = 0; mt < 2; mt++)
#pragma unroll
        for (int g = 0; g < 2; g++)
#pragma unroll
          for (int h = 0; h < 2; h++) {
            mma_f16(acc[mt][g*2 + h], ah[mt], &bh[g][h*2]);
            mma_f16(acc[mt][g*2 + h], al[mt], &bh[g][h*2]);
          }
    }
    __syncthreads();
  }

  sred[tid] = ss;
  __syncthreads();
  if (tid < 128)
    sinv[tid] = 1.f / fmaxf(sqrtf(sred[tid] + sred[tid+128] + sred[tid+256] + sred[tid+384]), 1e-12f);
  __syncthreads();

#pragma unroll
  for (int mt = 0; mt < 2; mt++)
#pragma unroll
    for (int nt = 0; nt < 4; nt++) {
      int row = mrow0 + mt*16 + gr;
      int cl = ncol0 + nt*8 + tc*2;
      int c = col0 + cl;
      if (c < KCLS) {
        float i0 = sinv[cl], i1 = sinv[cl+1];
        *(float2*)&out[((size_t)row*NB + n)*KCLS + c] =
            make_float2(acc[mt][nt][0]*i0, acc[mt][nt][1]*i1);
        *(float2*)&out[((size_t)(row+8)*NB + n)*KCLS + c] =
            make_float2(acc[mt][nt][2]*i0, acc[mt][nt][3]*i1);
      }
    }
}

// ========== launch ==========
extern "C" void kernel_launch(void* const* d_in, const int* in_sizes, int n_in,
                              void* d_out, int out_size) {
  const float* x        = (const float*)d_in[0];
  const float* Wmask    = (const float*)d_in[1];
  const float* Wout     = (const float*)d_in[2];
  const float* FForward = (const float*)d_in[3];
  const float* gamma    = (const float*)d_in[4];
  const float* beta     = (const float*)d_in[5];
  const float* fc1d     = (const float*)d_in[6];
  float* out        = (float*)d_out;
  float* out_logits = out + (size_t)Bsz*NB*OUTC;

  k_strip  <<<dim3(Bsz*Tt, Cch/32), 1024>>>(x);
  k_gmpa   <<<dim3(Bsz, NB), 256>>>(Wmask);
  k_gemmW  <<<dim3(4, NB), 256>>>(Wout);
  k_gemmF  <<<dim3(4, NB), 256>>>(FForward, out);
  k_bnstats<<<NB, OUTC>>>(gamma, beta);
  k_bnn    <<<dim3(Bsz, NB), 256>>>();
  k_logits_mma<<<dim3((KCLS + 127)/128, NB), 512>>>(fc1d, out_logits);
}